// round 1
// baseline (speedup 1.0000x reference)
#include <cuda_runtime.h>
#include <math.h>

// Problem constants
#define BATCH 16
#define DEC   256
#define ENC   2048
#define DM    512
#define C2    1024   // 2*DM, encoder feature dim

#define ECHUNK  4          // split of E for ctx partials
#define EPER    (ENC/ECHUNK) // 512

// Scratch (allocation-free rule: __device__ globals)
__device__ float g_venc[C2];
__device__ float g_score[BATCH * ENC];
__device__ float g_prob[BATCH * ENC];
__device__ float g_ctx_part[ECHUNK][BATCH][C2];

// ---------------------------------------------------------------------------
// Kernel 1: v_enc[c] = sum_m W_enc[c,m] * w_out[m]   (W_enc is (1024,512) row-major)
// ---------------------------------------------------------------------------
__global__ void venc_kernel(const float* __restrict__ W_enc,
                            const float* __restrict__ w_out) {
    int c = blockIdx.x * blockDim.x + threadIdx.x;
    if (c >= C2) return;
    const float4* row = (const float4*)(W_enc + (size_t)c * DM);
    const float4* w4  = (const float4*)w_out;
    float acc = 0.f;
#pragma unroll 8
    for (int i = 0; i < DM / 4; i++) {
        float4 a = row[i];
        float4 b = w4[i];
        acc += a.x * b.x + a.y * b.y + a.z * b.z + a.w * b.w;
    }
    g_venc[c] = acc;
}

// ---------------------------------------------------------------------------
// Kernel 2: score[b,e] = enc[b,e,:] . v_enc + log(mask[b,e]) -- one warp/row
// ---------------------------------------------------------------------------
__global__ void scores_kernel(const float* __restrict__ enc,
                              const float* __restrict__ emask) {
    int gwarp = (blockIdx.x * blockDim.x + threadIdx.x) >> 5;
    int lane  = threadIdx.x & 31;
    if (gwarp >= BATCH * ENC) return;
    const float4* row = (const float4*)(enc + (size_t)gwarp * C2);
    const float4* v   = (const float4*)g_venc;
    float acc = 0.f;
#pragma unroll
    for (int i = 0; i < 8; i++) {
        float4 a = row[lane + 32 * i];
        float4 b = v[lane + 32 * i];
        acc += a.x * b.x + a.y * b.y + a.z * b.z + a.w * b.w;
    }
#pragma unroll
    for (int o = 16; o > 0; o >>= 1)
        acc += __shfl_xor_sync(0xffffffffu, acc, o);
    if (lane == 0)
        g_score[gwarp] = acc + logf(emask[gwarp]);
}

// ---------------------------------------------------------------------------
// Kernel 3: softmax over E per batch. 16 blocks x 1024 threads, 2 elems/thread
// ---------------------------------------------------------------------------
__global__ void softmax_kernel() {
    int b = blockIdx.x;
    int t = threadIdx.x;            // 0..1023
    __shared__ float red[32];

    float s0 = g_score[b * ENC + t];
    float s1 = g_score[b * ENC + 1024 + t];

    // block max
    float m = fmaxf(s0, s1);
#pragma unroll
    for (int o = 16; o > 0; o >>= 1)
        m = fmaxf(m, __shfl_xor_sync(0xffffffffu, m, o));
    if ((t & 31) == 0) red[t >> 5] = m;
    __syncthreads();
    if (t < 32) {
        float v = red[t];
#pragma unroll
        for (int o = 16; o > 0; o >>= 1)
            v = fmaxf(v, __shfl_xor_sync(0xffffffffu, v, o));
        red[t] = v;
    }
    __syncthreads();
    m = red[0];

    float e0 = expf(s0 - m);
    float e1 = expf(s1 - m);

    // block sum
    float s = e0 + e1;
    __syncthreads();
#pragma unroll
    for (int o = 16; o > 0; o >>= 1)
        s += __shfl_xor_sync(0xffffffffu, s, o);
    if ((t & 31) == 0) red[t >> 5] = s;
    __syncthreads();
    if (t < 32) {
        float v = red[t];
#pragma unroll
        for (int o = 16; o > 0; o >>= 1)
            v += __shfl_xor_sync(0xffffffffu, v, o);
        red[t] = v;
    }
    __syncthreads();
    float inv = 1.f / red[0];

    g_prob[b * ENC + t]        = e0 * inv;
    g_prob[b * ENC + 1024 + t] = e1 * inv;
}

// ---------------------------------------------------------------------------
// Kernel 4: ctx partial: g_ctx_part[ch][b][c] = sum_{e in chunk} p[b,e]*enc[b,e,c]
// grid (4 col-tiles, ECHUNK, BATCH), 256 threads; no atomics -> deterministic
// ---------------------------------------------------------------------------
__global__ void ctx_partial_kernel(const float* __restrict__ enc) {
    int ct = blockIdx.x;   // 0..3 column tile (256 cols each)
    int ch = blockIdx.y;   // 0..3 e-chunk
    int b  = blockIdx.z;   // 0..15
    int t  = threadIdx.x;  // 0..255

    __shared__ float sp[EPER];
    sp[t]       = g_prob[b * ENC + ch * EPER + t];
    sp[t + 256] = g_prob[b * ENC + ch * EPER + 256 + t];
    __syncthreads();

    int c = ct * 256 + t;
    const float* base = enc + ((size_t)(b * ENC + ch * EPER)) * C2 + c;
    float acc = 0.f;
#pragma unroll 8
    for (int e = 0; e < EPER; e++)
        acc += sp[e] * base[(size_t)e * C2];
    g_ctx_part[ch][b][c] = acc;
}

// ---------------------------------------------------------------------------
// Kernel 5a: out_ctx[b,d,c] = sum_ch g_ctx_part[ch][b][c]   (float4, 16.8 MB)
// ---------------------------------------------------------------------------
__global__ void write_ctx_kernel(float4* __restrict__ out) {
    int i4 = blockIdx.x * blockDim.x + threadIdx.x;   // < 1048576
    if (i4 >= BATCH * DEC * C2 / 4) return;
    int row = i4 >> 8;           // (b,d) row, 256 float4 per row
    int c4  = i4 & 255;
    int b   = row >> 8;          // / DEC
    const float4* p0 = (const float4*)g_ctx_part[0][b];
    const float4* p1 = (const float4*)g_ctx_part[1][b];
    const float4* p2 = (const float4*)g_ctx_part[2][b];
    const float4* p3 = (const float4*)g_ctx_part[3][b];
    float4 a = p0[c4], x = p1[c4], y = p2[c4], z = p3[c4];
    float4 s;
    s.x = a.x + x.x + y.x + z.x;
    s.y = a.y + x.y + y.y + z.y;
    s.z = a.z + x.z + y.z + z.z;
    s.w = a.w + x.w + y.w + z.w;
    out[i4] = s;
}

// ---------------------------------------------------------------------------
// Kernel 5b: out_attn[b,d,e] = p[b,e]   (float4, 33.5 MB)
// ---------------------------------------------------------------------------
__global__ void write_attn_kernel(float4* __restrict__ out) {
    int i4 = blockIdx.x * blockDim.x + threadIdx.x;   // < 2097152
    if (i4 >= BATCH * DEC * ENC / 4) return;
    int row = i4 >> 9;           // (b,d) row, 512 float4 per row
    int e4  = i4 & 511;
    int b   = row >> 8;          // / DEC
    out[i4] = ((const float4*)g_prob)[b * 512 + e4];
}

// ---------------------------------------------------------------------------
// Launch: inputs (metadata order): decoder_states, decoder_mask,
//   encoder_states, encoder_mask, W_enc, W_dec, w_out, b_out
// Output: [context (B*DEC*C2) | attn_dist (B*DEC*ENC)] floats
// ---------------------------------------------------------------------------
extern "C" void kernel_launch(void* const* d_in, const int* in_sizes, int n_in,
                              void* d_out, int out_size) {
    const float* enc   = (const float*)d_in[2];
    const float* emask = (const float*)d_in[3];
    const float* W_enc = (const float*)d_in[4];
    const float* w_out = (const float*)d_in[6];

    float* out_ctx  = (float*)d_out;
    float* out_attn = (float*)d_out + (size_t)BATCH * DEC * C2;

    venc_kernel<<<C2 / 128, 128>>>(W_enc, w_out);

    // one warp per (b,e) row: 32768 warps, 8 warps/block -> 4096 blocks
    scores_kernel<<<(BATCH * ENC) / 8, 256>>>(enc, emask);

    softmax_kernel<<<BATCH, 1024>>>();

    dim3 g4(C2 / 256, ECHUNK, BATCH);
    ctx_partial_kernel<<<g4, 256>>>(enc);

    write_ctx_kernel<<<(BATCH * DEC * C2 / 4) / 256, 256>>>((float4*)out_ctx);
    write_attn_kernel<<<(BATCH * DEC * ENC / 4) / 256, 256>>>((float4*)out_attn);
}

// round 2
// speedup vs baseline: 1.2510x; 1.2510x over previous
#include <cuda_runtime.h>
#include <math.h>

// Problem constants
#define BATCH 16
#define DEC   256
#define ENC   2048
#define DM    512
#define C2    1024   // 2*DM, encoder feature dim

#define ECH   32            // E chunks for ctx partials
#define EPER  (ENC/ECH)     // 64 rows per chunk

// Scratch (allocation-free rule: __device__ globals)
__device__ float g_venc[C2];
__device__ float g_score[BATCH * ENC];
__device__ float g_prob[BATCH * ENC];
__device__ float4 g_ctx_part[ECH][BATCH][C2 / 4];  // 2 MB
__device__ float4 g_ctx[BATCH][C2 / 4];            // 64 KB

// ---------------------------------------------------------------------------
// Kernel 1: v_enc[c] = sum_m W_enc[c,m] * w_out[m]
// ---------------------------------------------------------------------------
__global__ void venc_kernel(const float* __restrict__ W_enc,
                            const float* __restrict__ w_out) {
    int c = blockIdx.x * blockDim.x + threadIdx.x;
    if (c >= C2) return;
    const float4* row = (const float4*)(W_enc + (size_t)c * DM);
    const float4* w4  = (const float4*)w_out;
    float acc = 0.f;
#pragma unroll 8
    for (int i = 0; i < DM / 4; i++) {
        float4 a = row[i];
        float4 b = w4[i];
        acc += a.x * b.x + a.y * b.y + a.z * b.z + a.w * b.w;
    }
    g_venc[c] = acc;
}

// ---------------------------------------------------------------------------
// Kernel 2: score[b,e] = enc[b,e,:] . v_enc + log(mask[b,e]) -- one warp/row
// ---------------------------------------------------------------------------
__global__ void scores_kernel(const float* __restrict__ enc,
                              const float* __restrict__ emask) {
    int gwarp = (blockIdx.x * blockDim.x + threadIdx.x) >> 5;
    int lane  = threadIdx.x & 31;
    if (gwarp >= BATCH * ENC) return;
    const float4* row = (const float4*)(enc + (size_t)gwarp * C2);
    const float4* v   = (const float4*)g_venc;
    float acc = 0.f;
#pragma unroll
    for (int i = 0; i < 8; i++) {
        float4 a = __ldg(row + lane + 32 * i);
        float4 b = v[lane + 32 * i];
        acc += a.x * b.x + a.y * b.y + a.z * b.z + a.w * b.w;
    }
#pragma unroll
    for (int o = 16; o > 0; o >>= 1)
        acc += __shfl_xor_sync(0xffffffffu, acc, o);
    if (lane == 0)
        g_score[gwarp] = acc + logf(emask[gwarp]);
}

// ---------------------------------------------------------------------------
// Kernel 3: softmax over E per batch. 16 blocks x 1024 threads
// ---------------------------------------------------------------------------
__global__ void softmax_kernel() {
    int b = blockIdx.x;
    int t = threadIdx.x;            // 0..1023
    __shared__ float red[32];

    float s0 = g_score[b * ENC + t];
    float s1 = g_score[b * ENC + 1024 + t];

    float m = fmaxf(s0, s1);
#pragma unroll
    for (int o = 16; o > 0; o >>= 1)
        m = fmaxf(m, __shfl_xor_sync(0xffffffffu, m, o));
    if ((t & 31) == 0) red[t >> 5] = m;
    __syncthreads();
    if (t < 32) {
        float v = red[t];
#pragma unroll
        for (int o = 16; o > 0; o >>= 1)
            v = fmaxf(v, __shfl_xor_sync(0xffffffffu, v, o));
        red[t] = v;
    }
    __syncthreads();
    m = red[0];

    float e0 = expf(s0 - m);
    float e1 = expf(s1 - m);

    float s = e0 + e1;
    __syncthreads();
#pragma unroll
    for (int o = 16; o > 0; o >>= 1)
        s += __shfl_xor_sync(0xffffffffu, s, o);
    if ((t & 31) == 0) red[t >> 5] = s;
    __syncthreads();
    if (t < 32) {
        float v = red[t];
#pragma unroll
        for (int o = 16; o > 0; o >>= 1)
            v += __shfl_xor_sync(0xffffffffu, v, o);
        red[t] = v;
    }
    __syncthreads();
    float inv = 1.f / red[0];

    g_prob[b * ENC + t]        = e0 * inv;
    g_prob[b * ENC + 1024 + t] = e1 * inv;
}

// ---------------------------------------------------------------------------
// Kernel 4: ctx partial v2 — float4 per thread across full row width.
// grid (ECH=32, BATCH=16) = 512 blocks, 256 threads.
// Each block: 64 rows x 1024 cols; thread t owns cols [4t, 4t+4).
// 64 independent float4 loads per thread -> high MLP, fully coalesced.
// ---------------------------------------------------------------------------
__global__ void ctx_partial_kernel(const float4* __restrict__ enc4) {
    int ch = blockIdx.x;   // 0..31 e-chunk
    int b  = blockIdx.y;   // 0..15
    int t  = threadIdx.x;  // 0..255 -> float4 column index

    __shared__ float sp[EPER];
    if (t < EPER) sp[t] = g_prob[b * ENC + ch * EPER + t];
    __syncthreads();

    const float4* base = enc4 + ((size_t)(b * ENC + ch * EPER)) * (C2 / 4) + t;
    float4 acc = make_float4(0.f, 0.f, 0.f, 0.f);
#pragma unroll 8
    for (int e = 0; e < EPER; e++) {
        float4 v = __ldg(base + (size_t)e * (C2 / 4));
        float p = sp[e];
        acc.x += p * v.x;
        acc.y += p * v.y;
        acc.z += p * v.z;
        acc.w += p * v.w;
    }
    g_ctx_part[ch][b][t] = acc;
}

// ---------------------------------------------------------------------------
// Kernel 4b: reduce 32 partials -> g_ctx[b][c4]. grid 16, block 256. ~2MB L2.
// ---------------------------------------------------------------------------
__global__ void ctx_reduce_kernel() {
    int b = blockIdx.x;
    int t = threadIdx.x;
    float4 acc = make_float4(0.f, 0.f, 0.f, 0.f);
#pragma unroll
    for (int ch = 0; ch < ECH; ch++) {
        float4 v = g_ctx_part[ch][b][t];
        acc.x += v.x; acc.y += v.y; acc.z += v.z; acc.w += v.w;
    }
    g_ctx[b][t] = acc;
}

// ---------------------------------------------------------------------------
// Kernel 5a: out_ctx[b,d,c] = g_ctx[b][c]  (broadcast over d, 16.8 MB write)
// ---------------------------------------------------------------------------
__global__ void write_ctx_kernel(float4* __restrict__ out) {
    int i4 = blockIdx.x * blockDim.x + threadIdx.x;   // < 1048576
    if (i4 >= BATCH * DEC * C2 / 4) return;
    int row = i4 >> 8;           // (b,d) row, 256 float4 per row
    int c4  = i4 & 255;
    int b   = row >> 8;          // / DEC
    out[i4] = g_ctx[b][c4];
}

// ---------------------------------------------------------------------------
// Kernel 5b: out_attn[b,d,e] = p[b,e]  (broadcast over d, 33.5 MB write)
// ---------------------------------------------------------------------------
__global__ void write_attn_kernel(float4* __restrict__ out) {
    int i4 = blockIdx.x * blockDim.x + threadIdx.x;   // < 2097152
    if (i4 >= BATCH * DEC * ENC / 4) return;
    int row = i4 >> 9;           // (b,d) row, 512 float4 per row
    int e4  = i4 & 511;
    int b   = row >> 8;          // / DEC
    out[i4] = ((const float4*)g_prob)[b * 512 + e4];
}

// ---------------------------------------------------------------------------
// Launch: inputs: decoder_states, decoder_mask, encoder_states, encoder_mask,
//   W_enc, W_dec, w_out, b_out
// Output: [context (B*DEC*C2) | attn_dist (B*DEC*ENC)] floats
// ---------------------------------------------------------------------------
extern "C" void kernel_launch(void* const* d_in, const int* in_sizes, int n_in,
                              void* d_out, int out_size) {
    const float* enc   = (const float*)d_in[2];
    const float* emask = (const float*)d_in[3];
    const float* W_enc = (const float*)d_in[4];
    const float* w_out = (const float*)d_in[6];

    float* out_ctx  = (float*)d_out;
    float* out_attn = (float*)d_out + (size_t)BATCH * DEC * C2;

    venc_kernel<<<C2 / 128, 128>>>(W_enc, w_out);

    scores_kernel<<<(BATCH * ENC) / 8, 256>>>(enc, emask);

    softmax_kernel<<<BATCH, 1024>>>();

    dim3 g4(ECH, BATCH);
    ctx_partial_kernel<<<g4, 256>>>((const float4*)enc);
    ctx_reduce_kernel<<<BATCH, 256>>>();

    write_ctx_kernel<<<(BATCH * DEC * C2 / 4) / 256, 256>>>((float4*)out_ctx);
    write_attn_kernel<<<(BATCH * DEC * ENC / 4) / 256, 256>>>((float4*)out_attn);
}

// round 5
// speedup vs baseline: 1.2604x; 1.0075x over previous
#include <cuda_runtime.h>
#include <math.h>

// Problem constants
#define BATCH 16
#define DEC   256
#define ENC   2048
#define DM    512
#define C2    1024   // 2*DM, encoder feature dim
#define C4    (C2/4) // 256 float4 per row

#define ECH   128           // E chunks
#define EPER  (ENC/ECH)     // 16 rows per chunk

#define CTX4  (BATCH * DEC * C2 / 4)   // 1048576 float4
#define ATT4  (BATCH * DEC * ENC / 4)  // 2097152 float4

// Scratch (allocation-free rule: __device__ globals)
__device__ float  g_venc[C2];
__device__ float  g_score[BATCH * ENC];
__device__ float  g_prob[BATCH * ENC];
__device__ float  g_m[ECH][BATCH];
__device__ float  g_z[ECH][BATCH];
__device__ float4 g_ctx_part[ECH][BATCH][C4];  // 8 MB
__device__ float4 g_ctx[BATCH][C4];            // 64 KB

// ---------------------------------------------------------------------------
// Kernel 1: v_enc[c] = sum_m W_enc[c,m] * w_out[m]
// ---------------------------------------------------------------------------
__global__ void venc_kernel(const float* __restrict__ W_enc,
                            const float* __restrict__ w_out) {
    int c = blockIdx.x * blockDim.x + threadIdx.x;
    if (c >= C2) return;
    const float4* row = (const float4*)(W_enc + (size_t)c * DM);
    const float4* w4  = (const float4*)w_out;
    float acc = 0.f;
#pragma unroll 8
    for (int i = 0; i < DM / 4; i++) {
        float4 a = row[i];
        float4 b = w4[i];
        acc += a.x * b.x + a.y * b.y + a.z * b.z + a.w * b.w;
    }
    g_venc[c] = acc;
}

// ---------------------------------------------------------------------------
// Kernel 2 (FUSED): per (chunk, batch) block:
//   - load EPER=16 enc rows into registers (1 float4 column slice per thread)
//   - per-row score = enc_row . venc  (smem partial-dot + full-warp reduce)
//   - local softmax: m_loc, w_e = exp(s_e - m_loc), z_loc
//   - ctx partial = sum_e w_e * row_e (registers; enc read exactly once)
// All warp collectives below execute with the ENTIRE warp active.
// ---------------------------------------------------------------------------
__global__ void fused_kernel(const float4* __restrict__ enc4,
                             const float* __restrict__ emask) {
    int ch = blockIdx.x;   // 0..127
    int b  = blockIdx.y;   // 0..15
    int t  = threadIdx.x;  // 0..255
    int lane = t & 31, wid = t >> 5;

    __shared__ float pd[EPER][256];   // 16 KB partial dots
    __shared__ float ss[EPER];        // masked scores
    __shared__ float sw[EPER];        // softmax weights

    float4 v4 = ((const float4*)g_venc)[t];

    const float4* base = enc4 + ((size_t)(b * ENC + ch * EPER)) * C4 + t;

    float4 rows[EPER];
#pragma unroll
    for (int e = 0; e < EPER; e++) {
        float4 r = __ldg(base + (size_t)e * C4);
        rows[e] = r;
        pd[e][t] = r.x * v4.x + r.y * v4.y + r.z * v4.z + r.w * v4.w;
    }
    __syncthreads();

    // 8 warps reduce 16 rows (2 per warp); whole warp active, full-warp shfl
#pragma unroll
    for (int k = 0; k < 2; k++) {
        int r = wid * 2 + k;
        float s = 0.f;
#pragma unroll
        for (int i = 0; i < 8; i++) s += pd[r][lane + 32 * i];
#pragma unroll
        for (int o = 16; o > 0; o >>= 1)
            s += __shfl_xor_sync(0xffffffffu, s, o);
        if (lane == 0) {
            int eg = b * ENC + ch * EPER + r;
            s += logf(emask[eg]);
            g_score[eg] = s;
            ss[r] = s;
        }
    }
    __syncthreads();

    // warp 0 (all 32 lanes active): local max, weights, z over 16 scores
    if (wid == 0) {
        float s = (lane < EPER) ? ss[lane] : -1e30f;
        float m = s;
#pragma unroll
        for (int o = 16; o > 0; o >>= 1)
            m = fmaxf(m, __shfl_xor_sync(0xffffffffu, m, o));
        float w = (lane < EPER) ? expf(s - m) : 0.f;
        if (lane < EPER) sw[lane] = w;
        float z = w;
#pragma unroll
        for (int o = 16; o > 0; o >>= 1)
            z += __shfl_xor_sync(0xffffffffu, z, o);
        if (lane == 0) {
            g_m[ch][b] = m;
            g_z[ch][b] = z;
        }
    }
    __syncthreads();

    float4 acc = make_float4(0.f, 0.f, 0.f, 0.f);
#pragma unroll
    for (int e = 0; e < EPER; e++) {
        float w = sw[e];
        acc.x += w * rows[e].x;
        acc.y += w * rows[e].y;
        acc.z += w * rows[e].z;
        acc.w += w * rows[e].w;
    }
    g_ctx_part[ch][b][t] = acc;
}

// ---------------------------------------------------------------------------
// Kernel 3 (COMBINE): per batch b:
//   M = max_ch m_ch;  Z = sum_ch z_ch * exp(m_ch - M)
//   ctx[b][c] = (sum_ch part_ch[c] * exp(m_ch - M)) / Z
//   prob[b][e] = exp(score[b][e] - M) / Z
// All shuffles full-warp (entire warp in the active region).
// ---------------------------------------------------------------------------
__global__ void combine_kernel() {
    int b = blockIdx.x;
    int t = threadIdx.x;   // 0..255
    int lane = t & 31, wid = t >> 5;

    __shared__ float sc[ECH];    // per-chunk scale exp(m_ch - M) / Z
    __shared__ float redm[8];
    __shared__ float redz[8];
    __shared__ float sMZ[2];

    float m_t = (t < ECH) ? g_m[t][b] : -1e30f;
    float z_t = (t < ECH) ? g_z[t][b] : 0.f;

    // per-warp max of m (all warps, all lanes active)
    float m = m_t;
#pragma unroll
    for (int o = 16; o > 0; o >>= 1)
        m = fmaxf(m, __shfl_xor_sync(0xffffffffu, m, o));
    if (lane == 0) redm[wid] = m;
    __syncthreads();

    // warp 0 finishes max with FULL warp active
    if (wid == 0) {
        float v = (lane < 8) ? redm[lane] : -1e30f;
#pragma unroll
        for (int o = 16; o > 0; o >>= 1)
            v = fmaxf(v, __shfl_xor_sync(0xffffffffu, v, o));
        if (lane == 0) sMZ[0] = v;
    }
    __syncthreads();
    float M = sMZ[0];

    // per-warp sum of z * exp(m - M)
    float zs = z_t * expf(m_t - M);
#pragma unroll
    for (int o = 16; o > 0; o >>= 1)
        zs += __shfl_xor_sync(0xffffffffu, zs, o);
    if (lane == 0) redz[wid] = zs;
    __syncthreads();

    if (wid == 0) {
        float v = (lane < 8) ? redz[lane] : 0.f;
#pragma unroll
        for (int o = 16; o > 0; o >>= 1)
            v += __shfl_xor_sync(0xffffffffu, v, o);
        if (lane == 0) sMZ[1] = v;
    }
    __syncthreads();
    float invZ = 1.f / sMZ[1];

    if (t < ECH) sc[t] = expf(m_t - M) * invZ;
    __syncthreads();

    // final ctx
    float4 acc = make_float4(0.f, 0.f, 0.f, 0.f);
#pragma unroll 8
    for (int ch = 0; ch < ECH; ch++) {
        float4 v = g_ctx_part[ch][b][t];
        float s = sc[ch];
        acc.x += s * v.x;
        acc.y += s * v.y;
        acc.z += s * v.z;
        acc.w += s * v.w;
    }
    g_ctx[b][t] = acc;

    // probs: 2048 per batch, 8 per thread
#pragma unroll
    for (int i = 0; i < 8; i++) {
        int e = t + 256 * i;
        g_prob[b * ENC + e] = expf(g_score[b * ENC + e] - M) * invZ;
    }
}

// ---------------------------------------------------------------------------
// Kernel 4 (WRITER): both broadcast outputs in one grid.
//   out_ctx[b,d,c]  = g_ctx[b][c]    (16.8 MB)
//   out_attn[b,d,e] = g_prob[b][e]   (33.5 MB)
// ---------------------------------------------------------------------------
__global__ void writer_kernel(float4* __restrict__ out_ctx,
                              float4* __restrict__ out_attn) {
    int i4 = blockIdx.x * blockDim.x + threadIdx.x;
    if (i4 < CTX4) {
        int row = i4 >> 8;         // 256 float4 per row
        int c4  = i4 & 255;
        int b   = row >> 8;        // / DEC
        out_ctx[i4] = g_ctx[b][c4];
    } else {
        int j4 = i4 - CTX4;
        if (j4 >= ATT4) return;
        int row = j4 >> 9;         // 512 float4 per row
        int e4  = j4 & 511;
        int b   = row >> 8;        // / DEC
        out_attn[j4] = ((const float4*)g_prob)[b * 512 + e4];
    }
}

// ---------------------------------------------------------------------------
// Launch. Inputs: decoder_states, decoder_mask, encoder_states, encoder_mask,
//   W_enc, W_dec, w_out, b_out
// Output: [context (B*DEC*C2) | attn_dist (B*DEC*ENC)] floats
// ---------------------------------------------------------------------------
extern "C" void kernel_launch(void* const* d_in, const int* in_sizes, int n_in,
                              void* d_out, int out_size) {
    const float* enc   = (const float*)d_in[2];
    const float* emask = (const float*)d_in[3];
    const float* W_enc = (const float*)d_in[4];
    const float* w_out = (const float*)d_in[6];

    float* out_ctx  = (float*)d_out;
    float* out_attn = (float*)d_out + (size_t)BATCH * DEC * C2;

    venc_kernel<<<C2 / 128, 128>>>(W_enc, w_out);

    dim3 gf(ECH, BATCH);
    fused_kernel<<<gf, 256>>>((const float4*)enc, emask);

    combine_kernel<<<BATCH, 256>>>();

    writer_kernel<<<(CTX4 + ATT4 + 255) / 256, 256>>>((float4*)out_ctx,
                                                      (float4*)out_attn);
}